// round 1
// baseline (speedup 1.0000x reference)
#include <cuda_runtime.h>
#include <math.h>

// ---------------- problem constants ----------------
#define kN    16
#define kC    80
#define kH    160
#define kW    160
#define kHW   (kH * kW)          // 25600
#define kCHW  (kC * kHW)         // 2048000
#define kPreK 1000
#define kPostK 200
#define kBins 65536
#define kCandCap (1 << 20)       // per-image candidate capacity (actual ~300k)
#define kGathCap 4096

__device__ __constant__ float kLogitThresh = -2.9444389791664403f; // log(0.05/0.95)
#define kClipDWH 4.135166556742356f                                 // log(1000/16)
#define kImgMax  1279.0f
#define kOffScale 1281.0f                                           // IMG + 1
#define kNmsThr  0.8f

// ---------------- device scratch (static; no allocation) ----------------
__device__ unsigned long long g_cand[kN][kCandCap];
__device__ unsigned int       g_hist[kN][kBins];
__device__ int                g_cnt[kN];
__device__ int                g_cutoff[kN];
__device__ unsigned long long g_gath[kN][kGathCap];
__device__ int                g_gcnt[kN];
__device__ unsigned long long g_top[kN][kPreK];

// ---------------- kernel 0: reset scratch ----------------
__global__ void k_init() {
    int t = blockIdx.x * blockDim.x + threadIdx.x;     // 4096 * 256 = 1,048,576 == kN*kBins
    ((unsigned int*)g_hist)[t] = 0u;
    if (t < kN) { g_cnt[t] = 0; g_gcnt[t] = 0; }
}

// ---------------- kernel 1: threshold + compact (the big read) ----------------
// pack: high32 = logit bits, low32 = idx (= hw*C + c)
__global__ __launch_bounds__(256) void k_score_pass(const float* __restrict__ cls) {
    int t = blockIdx.x * blockDim.x + threadIdx.x;
    int p = t * 4;                                      // < 32,768,000 fits int
    int n  = p / kCHW;
    int r  = p - n * kCHW;
    int c  = r / kHW;
    int hw = r - c * kHW;                               // 4-elem chunk never crosses c (kHW%4==0)

    float4 v = *(const float4*)(cls + p);
    float vals[4] = {v.x, v.y, v.z, v.w};

    unsigned long long lk[4];
    int m = 0;
#pragma unroll
    for (int k = 0; k < 4; k++) {
        if (vals[k] > kLogitThresh) {
            unsigned idx = (unsigned)((hw + k) * kC + c);
            lk[m++] = ((unsigned long long)__float_as_uint(vals[k]) << 32) | idx;
        }
    }
    // warp-aggregated append (whole warp is same image: 128 | kCHW)
    unsigned lane = threadIdx.x & 31;
    int incl = m;
#pragma unroll
    for (int d = 1; d < 32; d <<= 1) {
        int vv = __shfl_up_sync(0xffffffffu, incl, d);
        if (lane >= d) incl += vv;
    }
    int total = __shfl_sync(0xffffffffu, incl, 31);
    int base = 0;
    if (lane == 31 && total > 0) base = atomicAdd(&g_cnt[n], total);
    base = __shfl_sync(0xffffffffu, base, 31);
    int off = base + incl - m;
#pragma unroll
    for (int k = 0; k < 4; k++)
        if (k < m && off + k < kCandCap) g_cand[n][off + k] = lk[k];
}

// ---------------- kernel 2: dense sigmoid + histogram, rewrite keys ----------------
// key: high32 = score bits (positive float, monotone), low32 = ~idx (desc sort => idx asc ties)
__global__ __launch_bounds__(256) void k_score_candidates(const float* __restrict__ ctr) {
    int n = blockIdx.y;
    int cnt = min(g_cnt[n], kCandCap);
    for (int j = blockIdx.x * blockDim.x + threadIdx.x; j < cnt;
         j += gridDim.x * blockDim.x) {
        unsigned long long pk = g_cand[n][j];
        float logit = __uint_as_float((unsigned)(pk >> 32));
        unsigned idx = (unsigned)pk;
        int hw = idx / kC;
        float p  = 1.0f / (1.0f + expf(-logit));
        float cp = 1.0f / (1.0f + expf(-ctr[n * kHW + hw]));
        float s = p * cp;
        unsigned sb = __float_as_uint(s);
        atomicAdd(&g_hist[n][sb >> 14], 1u);
        g_cand[n][j] = ((unsigned long long)sb << 32) | (unsigned)(~idx);
    }
}

// ---------------- kernel 3: find cutoff bin for rank kPreK ----------------
__global__ __launch_bounds__(256) void k_find_cutoff() {
    int n = blockIdx.x, t = threadIdx.x;
    __shared__ unsigned ssum[256];
    const unsigned* h = g_hist[n];
    unsigned s = 0;
    int b0 = t * 256;
#pragma unroll 8
    for (int b = b0; b < b0 + 256; b++) s += h[b];
    ssum[t] = s;
    __syncthreads();
    if (t == 0) {
        unsigned cum = 0; int B = 0; bool found = false;
        for (int st = 255; st >= 0 && !found; st--) {
            unsigned ss = ssum[st];
            if (cum + ss >= (unsigned)kPreK) {
                for (int b = st * 256 + 255; b >= st * 256; b--) {
                    cum += h[b];
                    if (cum >= (unsigned)kPreK) { B = b; found = true; break; }
                }
            } else cum += ss;
        }
        g_cutoff[n] = B;   // 0 if fewer than kPreK candidates total
    }
}

// ---------------- kernel 4: gather candidates in bins >= cutoff ----------------
__global__ __launch_bounds__(256) void k_gather() {
    int n = blockIdx.y;
    int B = g_cutoff[n];
    int cnt = min(g_cnt[n], kCandCap);
    for (int j = blockIdx.x * blockDim.x + threadIdx.x; j < cnt;
         j += gridDim.x * blockDim.x) {
        unsigned long long key = g_cand[n][j];
        if ((int)(key >> 46) >= B) {                    // (score_bits >> 14)
            int pos = atomicAdd(&g_gcnt[n], 1);
            if (pos < kGathCap) g_gath[n][pos] = key;
        }
    }
}

// ---------------- kernel 5: bitonic sort 4096 desc, emit top 1000 ----------------
__global__ __launch_bounds__(1024) void k_sort_topk() {
    __shared__ unsigned long long keys[kGathCap];
    int n = blockIdx.x, t = threadIdx.x;
    int g = min(g_gcnt[n], kGathCap);
    for (int i = t; i < kGathCap; i += 1024)
        keys[i] = (i < g) ? g_gath[n][i] : 0ull;
    __syncthreads();
    for (int k = 2; k <= kGathCap; k <<= 1) {
        for (int j = k >> 1; j > 0; j >>= 1) {
            for (int i = t; i < kGathCap; i += 1024) {
                int l = i ^ j;
                if (l > i) {
                    unsigned long long a = keys[i], b = keys[l];
                    bool sw = ((i & k) == 0) ? (a < b) : (a > b); // descending overall
                    if (sw) { keys[i] = b; keys[l] = a; }
                }
            }
            __syncthreads();
        }
    }
    if (t < kPreK) g_top[n][t] = keys[t];
}

// ---------------- kernel 6: decode + greedy NMS + output ----------------
__global__ __launch_bounds__(1024) void k_nms_out(const float* __restrict__ reg,
                                                  const float* __restrict__ anchors,
                                                  float* __restrict__ out) {
    __shared__ float bx[kPreK][4];     // clipped boxes (output)
    __shared__ float obx[kPreK][4];    // class-offset boxes (NMS)
    __shared__ float sc[kPreK];        // sqrt(score)
    __shared__ unsigned char keep[kPreK];
    __shared__ int keptList[kPostK];
    __shared__ int s_nk, s_done, s_nv;

    int n = blockIdx.x, t = threadIdx.x;
    if (t == 0) { s_nk = 0; s_done = 0; s_nv = 0; }

    if (t < kPreK) {
        unsigned long long key = g_top[n][t];
        float s = __uint_as_float((unsigned)(key >> 32));
        bool valid = s > 0.0f;
        keep[t] = valid ? 1 : 0;
        if (valid) {
            unsigned idx = ~(unsigned)key;
            int loc = idx / kC;
            int cl  = idx - loc * kC;
            float a0 = anchors[loc * 4 + 0], a1 = anchors[loc * 4 + 1];
            float a2 = anchors[loc * 4 + 2], a3 = anchors[loc * 4 + 3];
            float w = a2 - a0 + 1.0f, h = a3 - a1 + 1.0f;
            float cx = a0 + 0.5f * w, cy = a1 + 0.5f * h;
            float d0 = reg[(n * 4 + 0) * kHW + loc];
            float d1 = reg[(n * 4 + 1) * kHW + loc];
            float d2 = reg[(n * 4 + 2) * kHW + loc];
            float d3 = reg[(n * 4 + 3) * kHW + loc];
            float dx = d0 / 10.0f, dy = d1 / 10.0f;
            float dw = fminf(d2 / 5.0f, kClipDWH);
            float dh = fminf(d3 / 5.0f, kClipDWH);
            float pcx = dx * w + cx, pcy = dy * h + cy;
            float pw = expf(dw) * w, ph = expf(dh) * h;
            float x1 = pcx - 0.5f * pw, y1 = pcy - 0.5f * ph;
            float x2 = pcx + 0.5f * pw - 1.0f, y2 = pcy + 0.5f * ph - 1.0f;
            x1 = fminf(fmaxf(x1, 0.0f), kImgMax);
            y1 = fminf(fmaxf(y1, 0.0f), kImgMax);
            x2 = fminf(fmaxf(x2, 0.0f), kImgMax);
            y2 = fminf(fmaxf(y2, 0.0f), kImgMax);
            bx[t][0] = x1; bx[t][1] = y1; bx[t][2] = x2; bx[t][3] = y2;
            float off = (float)(cl + 1) * kOffScale;
            obx[t][0] = x1 + off; obx[t][1] = y1 + off;
            obx[t][2] = x2 + off; obx[t][3] = y2 + off;
            sc[t] = sqrtf(s);
        }
    }
    __syncthreads();
    // valid entries are a prefix (sorted desc, padding keys are 0)
    if (t < kPreK && keep[t] && (t == kPreK - 1 || !keep[t + 1])) s_nv = t + 1;
    __syncthreads();
    int nv = s_nv;

    for (int i = 0; i < nv; i++) {
        __syncthreads();
        if (s_done) break;          // uniform smem reads -> convergent control flow
        if (!keep[i]) continue;
        if (t == 0) {
            keptList[s_nk] = i;
            s_nk = s_nk + 1;
            if (s_nk >= kPostK) s_done = 1;
        }
        if (t > i && t < nv && keep[t]) {
            float ix1 = fmaxf(obx[i][0], obx[t][0]);
            float iy1 = fmaxf(obx[i][1], obx[t][1]);
            float ix2 = fminf(obx[i][2], obx[t][2]);
            float iy2 = fminf(obx[i][3], obx[t][3]);
            float inter = fmaxf(ix2 - ix1, 0.0f) * fmaxf(iy2 - iy1, 0.0f);
            float aa = fmaxf(obx[i][2] - obx[i][0], 0.0f) * fmaxf(obx[i][3] - obx[i][1], 0.0f);
            float ab = fmaxf(obx[t][2] - obx[t][0], 0.0f) * fmaxf(obx[t][3] - obx[t][1], 0.0f);
            float iou = inter / fmaxf(aa + ab - inter, 1e-9f);
            if (iou > kNmsThr) keep[t] = 0;
        }
    }
    __syncthreads();

    if (t < kPostK) {
        float* o = out + ((long)n * kPostK + t) * 5;
        if (t < s_nk) {
            int i = keptList[t];
            o[0] = bx[i][0]; o[1] = bx[i][1]; o[2] = bx[i][2]; o[3] = bx[i][3];
            o[4] = sc[i];
        } else {
            o[0] = 0.0f; o[1] = 0.0f; o[2] = 0.0f; o[3] = 0.0f; o[4] = 0.0f;
        }
    }
}

// ---------------- launcher ----------------
extern "C" void kernel_launch(void* const* d_in, const int* in_sizes, int n_in,
                              void* d_out, int out_size) {
    const float* cls = (const float*)d_in[0];   // [16,80,160,160]
    const float* reg = (const float*)d_in[1];   // [16,4,160,160]
    const float* ctr = (const float*)d_in[2];   // [16,1,160,160]
    const float* anc = (const float*)d_in[3];   // [25600,4]
    float* out = (float*)d_out;                 // [16,200,5]

    k_init<<<4096, 256>>>();
    k_score_pass<<<(kN * kCHW / 4) / 256, 256>>>(cls);       // 32000 blocks
    k_score_candidates<<<dim3(64, kN), 256>>>(ctr);
    k_find_cutoff<<<kN, 256>>>();
    k_gather<<<dim3(64, kN), 256>>>();
    k_sort_topk<<<kN, 1024>>>();
    k_nms_out<<<kN, 1024>>>(reg, anc, out);
}